// round 10
// baseline (speedup 1.0000x reference)
#include <cuda_runtime.h>
#include <math.h>

// ---- problem dims ----
#define S_   512
#define B_   2048
#define GL_  32
#define OL_  20
#define M_   32
#define C_   16
#define GM_  64
#define OM_  20
#define GR_  128
#define OR_  38
#define IM_  384
#define IR_  768
#define EPSF 1e-5f
#define LC_  8        // leaf batch chunks (256 rows each)
#define MC_  8        // mid batch chunks (256 rows each)
#define PX_  257      // leaf x smem col-major pad (257 % 32 == 1 -> conflict-free)

typedef unsigned long long ull;

// ---- scratch ----
// TRANSPOSED intermediates: [feature][batch] for coalesced consumer reads.
__device__ float g_leaf_h[S_ * OL_ * B_];        // [s*20+o][b]
__device__ float g_leaf_part[S_ * LC_ * 40];     // [(s*8+chunk)][sum20|sq20]
__device__ float g_Wmid[M_ * IM_ * OM_];
__device__ float g_bmid[M_ * OM_];
__device__ float g_mid_h[M_ * OM_ * B_];         // [m*20+o][b]
__device__ float g_mid_part[M_ * MC_ * OM_ * 2];
__device__ float g_root_part[17 * 40 * B_];      // [kc][oo][b], chunk 16 = genes

// ---- packed f32x2 helpers ----
__device__ __forceinline__ ull pack2(float lo, float hi) {
    ull r; asm("mov.b64 %0, {%1, %2};" : "=l"(r) : "f"(lo), "f"(hi)); return r;
}
__device__ __forceinline__ ull dup2(float v) {
    ull r; asm("mov.b64 %0, {%1, %1};" : "=l"(r) : "f"(v)); return r;
}
__device__ __forceinline__ void unpack2(ull v, float& lo, float& hi) {
    asm("mov.b64 {%0, %1}, %2;" : "=f"(lo), "=f"(hi) : "l"(v));
}
__device__ __forceinline__ void fma2(ull& d, ull a, ull b) {
    asm("fma.rn.f32x2 %0, %1, %2, %3;" : "=l"(d) : "l"(a), "l"(b), "l"(d));
}

// fast tanh: 1 - 2/(exp(2x)+1), ~2e-7 abs error
__device__ __forceinline__ float ftanh(float x) {
    float e;
    asm("ex2.approx.f32 %0, %1;" : "=f"(e) : "f"(x * 2.885390081777927f));
    float r;
    asm("rcp.approx.f32 %0, %1;" : "=f"(r) : "f"(e + 1.0f));
    return fmaf(-2.f, r, 1.f);
}
__device__ __forceinline__ ull ftanh2(ull v) {
    float a, b; unpack2(v, a, b);
    return pack2(ftanh(a), ftanh(b));
}

// ============================================================================
// Kernel 1: leaf. grid(LC_=8, 512): 256-row chunk x subsystem. 256 thr,
// ONE row per thread. x staged via col-major smem (conflict-free).
// Writes g_leaf_h TRANSPOSED [s*20+o][b] and per-chunk partial stats.
// ============================================================================
__global__ __launch_bounds__(256) void k_leaf(
    const float* __restrict__ x_leaf, const float* __restrict__ W_leaf,
    const float* __restrict__ b_leaf)
{
    const int c = blockIdx.x;
    const int s = blockIdx.y;
    const int tid = threadIdx.x;
    const int R = c * 256;
    __shared__ __align__(16) float sW[GL_ * OL_];
    __shared__ __align__(16) ull sBp[10];
    __shared__ float sX[GL_ * PX_];                 // col-major [i][row]
    __shared__ float sRed[8 * 40];

    for (int i = tid; i < GL_ * OL_; i += 256) sW[i] = W_leaf[s * GL_ * OL_ + i];
    if (tid < 10)
        sBp[tid] = pack2(b_leaf[s * OL_ + tid * 2], b_leaf[s * OL_ + tid * 2 + 1]);

    // stage 256 rows x 32 floats, coalesced -> col-major smem
    const float4* gx = (const float4*)(x_leaf + ((long)s * B_ + R) * GL_);
#pragma unroll
    for (int k = 0; k < 8; k++) {
        const int f4 = tid + k * 256;               // 2048 float4 total
        const int bl = f4 >> 3;                     // row 0..255
        const int i0 = (f4 & 7) * 4;                // col 0,4,..,28
        float4 v = gx[f4];
        sX[(i0 + 0) * PX_ + bl] = v.x;
        sX[(i0 + 1) * PX_ + bl] = v.y;
        sX[(i0 + 2) * PX_ + bl] = v.z;
        sX[(i0 + 3) * PX_ + bl] = v.w;
    }
    __syncthreads();

    ull acc[10];
#pragma unroll
    for (int p = 0; p < 10; p++) acc[p] = sBp[p];

#pragma unroll 4
    for (int i = 0; i < GL_; i++) {
        const ull xd = dup2(sX[i * PX_ + tid]);     // conflict-free LDS.32
        const ulonglong2* wq = (const ulonglong2*)&sW[i * OL_];  // broadcast
#pragma unroll
        for (int q = 0; q < 5; q++) {
            ulonglong2 w2 = wq[q];
            fma2(acc[2*q+0], xd, w2.x);
            fma2(acc[2*q+1], xd, w2.y);
        }
    }

    // tanh + stats + transposed store (warp stores 128B contiguous per feature)
    const long bg = (long)R + tid;
    float s20[OL_], q20[OL_];
#pragma unroll
    for (int p = 0; p < 10; p++) {
        ull h = ftanh2(acc[p]);
        float lo, hi; unpack2(h, lo, hi);
        g_leaf_h[((long)s * OL_ + 2*p+0) * B_ + bg] = lo;
        g_leaf_h[((long)s * OL_ + 2*p+1) * B_ + bg] = hi;
        s20[2*p] = lo; s20[2*p+1] = hi;
        q20[2*p] = lo * lo; q20[2*p+1] = hi * hi;
    }
#pragma unroll
    for (int o = 0; o < OL_; o++) {
        for (int off = 16; off > 0; off >>= 1) {
            s20[o] += __shfl_down_sync(0xffffffffu, s20[o], off);
            q20[o] += __shfl_down_sync(0xffffffffu, q20[o], off);
        }
    }
    const int warp = tid >> 5, lane = tid & 31;
    if (lane == 0) {
#pragma unroll
        for (int o = 0; o < OL_; o++) { sRed[warp*40+o] = s20[o]; sRed[warp*40+20+o] = q20[o]; }
    }
    __syncthreads();
    if (tid < OL_) {
        float s1 = 0.f, s2 = 0.f;
        for (int w = 0; w < 8; w++) { s1 += sRed[w*40+tid]; s2 += sRed[w*40+20+tid]; }
        g_leaf_part[(s * LC_ + c) * 40 + tid]      = s1;
        g_leaf_part[(s * LC_ + c) * 40 + 20 + tid] = s2;
    }
}

// ============================================================================
// Kernel 2: finalize leaf BN + fold into mid weights/bias. grid=32 (per m).
// ============================================================================
__global__ __launch_bounds__(256) void k_prep_mid(
    const float* __restrict__ W_mid, const float* __restrict__ b_mid,
    const float* __restrict__ gam, const float* __restrict__ bet)
{
    const int m = blockIdx.x;
    const int tid = threadIdx.x;
    __shared__ float sA[C_ * OL_], sC[C_ * OL_];

    for (int idx = tid; idx < C_ * OL_; idx += 256) {   // grid-stride (320 > 256)
        const int s = m * C_ + idx / OL_;
        const int o = idx % OL_;
        float s1 = 0.f, s2 = 0.f;
#pragma unroll
        for (int ch = 0; ch < LC_; ch++) {
            s1 += g_leaf_part[(s * LC_ + ch) * 40 + o];
            s2 += g_leaf_part[(s * LC_ + ch) * 40 + 20 + o];
        }
        const float mean = s1 * (1.f / B_);
        const float var  = s2 * (1.f / B_) - mean * mean;
        const float a = gam[s * OL_ + o] * rsqrtf(var + EPSF);
        sA[idx] = a;
        sC[idx] = bet[s * OL_ + o] - mean * a;
    }
    __syncthreads();

    for (int idx = tid; idx < IM_ * OM_; idx += 256) {
        const int i = idx / OM_;
        float a = (i < GM_) ? 1.f : sA[i - GM_];
        g_Wmid[m * IM_ * OM_ + idx] = a * W_mid[m * IM_ * OM_ + idx];
    }
    const int warp = tid >> 5, lane = tid & 31;
    for (int o = warp; o < OM_; o += 8) {
        float p = 0.f;
        for (int i = GM_ + lane; i < IM_; i += 32)
            p = fmaf(sC[i - GM_], W_mid[m * IM_ * OM_ + i * OM_ + o], p);
        for (int off = 16; off > 0; off >>= 1)
            p += __shfl_down_sync(0xffffffffu, p, off);
        if (lane == 0) g_bmid[m * OM_ + o] = b_mid[m * OM_ + o] + p;
    }
}

// ============================================================================
// Kernel 3: mid. grid(MC_=8, 32), 256 thr, ONE row per thread (b=chunk*256+tid).
// Children read coalesced LDG.32 from transposed g_leaf_h.
// Writes g_mid_h TRANSPOSED [m*20+o][b] + partial stats.
// ============================================================================
__global__ __launch_bounds__(256) void k_mid(const float* __restrict__ x_mid)
{
    const int chunk = blockIdx.x;
    const int m = blockIdx.y;
    const int tid = threadIdx.x;
    const int b = chunk * 256 + tid;

    __shared__ __align__(16) float sW[IM_ * OM_];
    __shared__ __align__(16) ull sBp[10];
    __shared__ float sRed[8 * 40];

    for (int i = tid; i < IM_ * OM_; i += 256) sW[i] = g_Wmid[m * IM_ * OM_ + i];
    if (tid < 10)
        sBp[tid] = pack2(g_bmid[m * OM_ + tid * 2], g_bmid[m * OM_ + tid * 2 + 1]);
    __syncthreads();

    ull acc[10];
#pragma unroll
    for (int p = 0; p < 10; p++) acc[p] = sBp[p];

    // genes (rows 0..63): own row, 16 LDG.128 (row-local, L1-resident)
    {
        const float4* xm = (const float4*)(x_mid + ((long)m * B_ + b) * GM_);
#pragma unroll 2
        for (int i4 = 0; i4 < GM_ / 4; i4++) {
            float4 v = xm[i4];
            float xs[4] = { v.x, v.y, v.z, v.w };
#pragma unroll
            for (int cc = 0; cc < 4; cc++) {
                const ull xd = dup2(xs[cc]);
                const ulonglong2* wq = (const ulonglong2*)&sW[(i4 * 4 + cc) * OM_];
#pragma unroll
                for (int q = 0; q < 5; q++) {
                    ulonglong2 w2 = wq[q];
                    fma2(acc[2*q+0], xd, w2.x);
                    fma2(acc[2*q+1], xd, w2.y);
                }
            }
        }
    }
    // children (rows 64..383): coalesced LDG.32 from transposed g_leaf_h
#pragma unroll 1
    for (int j = 0; j < C_; j++) {
        const long fbase = ((long)(m * C_ + j)) * OL_;
        const int rbase = GM_ + j * OL_;
#pragma unroll
        for (int e = 0; e < OL_; e++) {
            const ull xd = dup2(g_leaf_h[(fbase + e) * B_ + b]);
            const ulonglong2* wq = (const ulonglong2*)&sW[(rbase + e) * OM_];
#pragma unroll
            for (int q = 0; q < 5; q++) {
                ulonglong2 w2 = wq[q];
                fma2(acc[2*q+0], xd, w2.x);
                fma2(acc[2*q+1], xd, w2.y);
            }
        }
    }

    float s20[OM_], q20[OM_];
#pragma unroll
    for (int p = 0; p < 10; p++) {
        ull h = ftanh2(acc[p]);
        float lo, hi; unpack2(h, lo, hi);
        g_mid_h[((long)m * OM_ + 2*p+0) * B_ + b] = lo;
        g_mid_h[((long)m * OM_ + 2*p+1) * B_ + b] = hi;
        s20[2*p] = lo; s20[2*p+1] = hi;
        q20[2*p] = lo * lo; q20[2*p+1] = hi * hi;
    }
#pragma unroll
    for (int o = 0; o < OM_; o++) {
        for (int off = 16; off > 0; off >>= 1) {
            s20[o] += __shfl_down_sync(0xffffffffu, s20[o], off);
            q20[o] += __shfl_down_sync(0xffffffffu, q20[o], off);
        }
    }
    const int warp = tid >> 5, lane = tid & 31;
    if (lane == 0) {
#pragma unroll
        for (int o = 0; o < OM_; o++) { sRed[warp*40+o] = s20[o]; sRed[warp*40+20+o] = q20[o]; }
    }
    __syncthreads();
    if (tid < OM_) {
        float s1 = 0.f, s2 = 0.f;
        for (int w = 0; w < 8; w++) { s1 += sRed[w*40+tid]; s2 += sRed[w*40+20+tid]; }
        g_mid_part[((m * MC_ + chunk) * OM_ + tid) * 2 + 0] = s1;
        g_mid_part[((m * MC_ + chunk) * OM_ + tid) * 2 + 1] = s2;
    }
}

// ============================================================================
// Kernel 4: root partials, merged. grid(17, 16), 128 thr, thread per b.
// kc<16: 40 mid-child features with inline BN finalize (interleaved FMA).
// kc==16: 128 gene features from x_root.
// Partials written transposed [kc][oo][b].
// ============================================================================
__global__ __launch_bounds__(128) void k_root(
    const float* __restrict__ x_root, const float* __restrict__ W_root,
    const float* __restrict__ gam, const float* __restrict__ bet)
{
    const int kc = blockIdx.x;
    const int bc = blockIdx.y;
    const int tid = threadIdx.x;
    const int b = bc * 128 + tid;

    __shared__ __align__(16) float sW[GR_ * 40];    // big enough for gene path
    __shared__ float sA[40], sC[40];

    ull acc[20];
#pragma unroll
    for (int p = 0; p < 20; p++) acc[p] = 0ull;

    if (kc < 16) {
        if (tid < 40) {                             // inline mid-BN finalize
            const int g = kc * 40 + tid;            // child idx 0..639
            const int mm = g / OM_, o = g % OM_;
            float s1 = 0.f, s2 = 0.f;
#pragma unroll
            for (int ch = 0; ch < MC_; ch++) {
                s1 += g_mid_part[((mm * MC_ + ch) * OM_ + o) * 2 + 0];
                s2 += g_mid_part[((mm * MC_ + ch) * OM_ + o) * 2 + 1];
            }
            const float mean = s1 * (1.f / B_);
            const float var  = s2 * (1.f / B_) - mean * mean;
            const float a = gam[g] * rsqrtf(var + EPSF);
            sA[tid] = a;
            sC[tid] = bet[g] - mean * a;
        }
        for (int idx = tid; idx < 40 * 40; idx += 128) {
            const int kk = idx / 40, oo = idx % 40;
            sW[idx] = (oo < OR_) ? W_root[(GR_ + kc * 40 + kk) * OR_ + oo] : 0.f;
        }
        __syncthreads();

#pragma unroll 4
        for (int kk = 0; kk < 40; kk++) {
            const float x = g_mid_h[((long)(kc * 40 + kk)) * B_ + b];   // coalesced
            const ull xd = dup2(fmaf(x, sA[kk], sC[kk]));
            const ulonglong2* wq = (const ulonglong2*)&sW[kk * 40];
#pragma unroll
            for (int q = 0; q < 10; q++) {
                ulonglong2 w2 = wq[q];
                fma2(acc[2*q+0], xd, w2.x);
                fma2(acc[2*q+1], xd, w2.y);
            }
        }
    } else {
        for (int idx = tid; idx < GR_ * 40; idx += 128) {
            const int kk = idx / 40, oo = idx % 40;
            sW[idx] = (oo < OR_) ? W_root[kk * OR_ + oo] : 0.f;
        }
        __syncthreads();

        const float4* px = (const float4*)(x_root + (long)b * GR_);
#pragma unroll 1
        for (int k4 = 0; k4 < GR_ / 4; k4++) {
            float4 v = px[k4];
            float xs[4] = { v.x, v.y, v.z, v.w };
#pragma unroll
            for (int cc = 0; cc < 4; cc++) {
                const ull xd = dup2(xs[cc]);
                const ulonglong2* wq = (const ulonglong2*)&sW[(k4 * 4 + cc) * 40];
#pragma unroll
                for (int q = 0; q < 10; q++) {
                    ulonglong2 w2 = wq[q];
                    fma2(acc[2*q+0], xd, w2.x);
                    fma2(acc[2*q+1], xd, w2.y);
                }
            }
        }
    }

#pragma unroll
    for (int p = 0; p < 20; p++) {
        float lo, hi; unpack2(acc[p], lo, hi);
        g_root_part[((long)(kc * 40 + 2*p+0)) * B_ + b] = lo;       // coalesced
        g_root_part[((long)(kc * 40 + 2*p+1)) * B_ + b] = hi;
    }
}

// ============================================================================
// Kernel 5: root finalize: combine 17 partials + bias + tanh + BN stats +
// normalize + write out. grid(38) — one block per output column.
// ============================================================================
__global__ __launch_bounds__(256) void k_rootfin(
    const float* __restrict__ b_root, const float* __restrict__ gam,
    const float* __restrict__ bet, float* __restrict__ out)
{
    const int o = blockIdx.x;
    const int tid = threadIdx.x;
    const float bias = b_root[o];

    float h[8];
    float s1 = 0.f, s2 = 0.f;
#pragma unroll
    for (int w = 0; w < 8; w++) {
        const int b = w * 256 + tid;
        float v = bias;
#pragma unroll
        for (int kc = 0; kc < 17; kc++)
            v += g_root_part[((long)(kc * 40 + o)) * B_ + b];       // coalesced
        const float t = ftanh(v);
        h[w] = t;
        s1 += t; s2 = fmaf(t, t, s2);
    }
    for (int off = 16; off > 0; off >>= 1) {
        s1 += __shfl_down_sync(0xffffffffu, s1, off);
        s2 += __shfl_down_sync(0xffffffffu, s2, off);
    }
    __shared__ float r1[8], r2[8];
    __shared__ float sAC[2];
    if ((tid & 31) == 0) { r1[tid >> 5] = s1; r2[tid >> 5] = s2; }
    __syncthreads();
    if (tid == 0) {
        float t1 = 0.f, t2 = 0.f;
        for (int w = 0; w < 8; w++) { t1 += r1[w]; t2 += r2[w]; }
        const float mean = t1 * (1.f / B_);
        const float var  = t2 * (1.f / B_) - mean * mean;
        const float a = gam[o] * rsqrtf(var + EPSF);
        sAC[0] = a;
        sAC[1] = bet[o] - mean * a;
    }
    __syncthreads();
    const float a = sAC[0], c = sAC[1];
#pragma unroll
    for (int w = 0; w < 8; w++) {
        const int b = w * 256 + tid;
        out[(long)b * OR_ + o] = fmaf(h[w], a, c);
    }
}

// ============================================================================
extern "C" void kernel_launch(void* const* d_in, const int* in_sizes, int n_in,
                              void* d_out, int out_size)
{
    const float* x_leaf = (const float*)d_in[0];
    const float* x_mid  = (const float*)d_in[1];
    const float* x_root = (const float*)d_in[2];
    const float* W_leaf = (const float*)d_in[3];
    const float* b_leaf = (const float*)d_in[4];
    const float* gleaf  = (const float*)d_in[5];
    const float* beleaf = (const float*)d_in[6];
    const float* W_mid  = (const float*)d_in[7];
    const float* b_mid  = (const float*)d_in[8];
    const float* gmid   = (const float*)d_in[9];
    const float* bemid  = (const float*)d_in[10];
    const float* W_root = (const float*)d_in[11];
    const float* b_root = (const float*)d_in[12];
    const float* groot  = (const float*)d_in[13];
    const float* beroot = (const float*)d_in[14];
    float* out = (float*)d_out;

    k_leaf<<<dim3(LC_, S_), 256>>>(x_leaf, W_leaf, b_leaf);
    k_prep_mid<<<M_, 256>>>(W_mid, b_mid, gleaf, beleaf);
    k_mid<<<dim3(MC_, M_), 256>>>(x_mid);
    k_root<<<dim3(17, 16), 128>>>(x_root, W_root, gmid, bemid);
    k_rootfin<<<OR_, 256>>>(b_root, groot, beroot, out);
}

// round 11
// speedup vs baseline: 1.1307x; 1.1307x over previous
#include <cuda_runtime.h>
#include <cuda_fp16.h>
#include <math.h>

// ---- problem dims ----
#define S_   512
#define B_   2048
#define GL_  32
#define OL_  20
#define M_   32
#define C_   16
#define GM_  64
#define OM_  20
#define GR_  128
#define OR_  38
#define IM_  384
#define IR_  768
#define EPSF 1e-5f
#define MC_  8        // mid batch chunks (256 rows each)
#define PX_  258      // leaf x smem col-major pad (even -> 8B-aligned LDS.64)

typedef unsigned long long ull;

// ---- scratch ----
// TRANSPOSED fp16 intermediates: [feature][batch]; 42MB+2.6MB -> L2-resident.
__device__ __half g_leaf_h[S_ * OL_ * B_];       // [s*20+o][b]
__device__ float  g_leaf_part[S_ * 2 * 40];      // [(s*2+chunk)][sum20|sq20]
__device__ float  g_Wmid[M_ * IM_ * OM_];
__device__ float  g_bmid[M_ * OM_];
__device__ __half g_mid_h[M_ * OM_ * B_];        // [m*20+o][b]
__device__ float  g_mid_part[M_ * MC_ * OM_ * 2];
__device__ float  g_root_part[17 * 40 * B_];     // [kc][oo][b], chunk 16 = genes

// ---- packed f32x2 helpers ----
__device__ __forceinline__ ull pack2(float lo, float hi) {
    ull r; asm("mov.b64 %0, {%1, %2};" : "=l"(r) : "f"(lo), "f"(hi)); return r;
}
__device__ __forceinline__ ull dup2(float v) {
    ull r; asm("mov.b64 %0, {%1, %1};" : "=l"(r) : "f"(v)); return r;
}
__device__ __forceinline__ void unpack2(ull v, float& lo, float& hi) {
    asm("mov.b64 {%0, %1}, %2;" : "=f"(lo), "=f"(hi) : "l"(v));
}
__device__ __forceinline__ void fma2(ull& d, ull a, ull b) {
    asm("fma.rn.f32x2 %0, %1, %2, %3;" : "=l"(d) : "l"(a), "l"(b), "l"(d));
}
__device__ __forceinline__ ull add2(ull a, ull b) {
    ull r; asm("add.rn.f32x2 %0, %1, %2;" : "=l"(r) : "l"(a), "l"(b)); return r;
}

// fast tanh: 1 - 2/(exp(2x)+1), ~2e-7 abs error
__device__ __forceinline__ float ftanh(float x) {
    float e;
    asm("ex2.approx.f32 %0, %1;" : "=f"(e) : "f"(x * 2.885390081777927f));
    float r;
    asm("rcp.approx.f32 %0, %1;" : "=f"(r) : "f"(e + 1.0f));
    return fmaf(-2.f, r, 1.f);
}
__device__ __forceinline__ ull ftanh2(ull v) {
    float a, b; unpack2(v, a, b);
    return pack2(ftanh(a), ftanh(b));
}

// ============================================================================
// Kernel 1: leaf. grid(2, 512): chunk c (1024 rows) x subsystem s. 128 thr,
// 2 adjacent rows/thread, 4 stages of 256 rows staged via col-major smem.
// Writes g_leaf_h TRANSPOSED fp16 [s*20+o][b]; stats from ROUNDED values.
// ============================================================================
__global__ __launch_bounds__(128) void k_leaf(
    const float* __restrict__ x_leaf, const float* __restrict__ W_leaf,
    const float* __restrict__ b_leaf)
{
    const int c = blockIdx.x;
    const int s = blockIdx.y;
    const int tid = threadIdx.x;
    __shared__ __align__(16) float sW[GL_ * OL_];
    __shared__ __align__(16) ull sBp[10];
    __shared__ __align__(16) float sX[GL_ * PX_];   // col-major [i][row]
    __shared__ float sRed[4 * 40];

    for (int i = tid; i < GL_ * OL_; i += 128) sW[i] = W_leaf[s * GL_ * OL_ + i];
    if (tid < 10)
        sBp[tid] = pack2(b_leaf[s * OL_ + tid * 2], b_leaf[s * OL_ + tid * 2 + 1]);

    ull sum[10], sq[10];
#pragma unroll
    for (int p = 0; p < 10; p++) { sum[p] = 0ull; sq[p] = 0ull; }

#pragma unroll 1
    for (int st = 0; st < 4; st++) {
        const int R = c * 1024 + st * 256;          // stage base row
        __syncthreads();
        // stage 256 rows x 32 floats, coalesced -> col-major smem
        const float4* gx = (const float4*)(x_leaf + ((long)s * B_ + R) * GL_);
#pragma unroll
        for (int k = 0; k < 16; k++) {
            const int f4 = tid + k * 128;           // 2048 float4 total
            const int bl = f4 >> 3;                 // row 0..255
            const int i0 = (f4 & 7) * 4;            // col 0,4,..28
            float4 v = gx[f4];
            sX[(i0 + 0) * PX_ + bl] = v.x;
            sX[(i0 + 1) * PX_ + bl] = v.y;
            sX[(i0 + 2) * PX_ + bl] = v.z;
            sX[(i0 + 3) * PX_ + bl] = v.w;
        }
        __syncthreads();

        const int bl = 2 * tid;                     // local rows bl, bl+1
        ull acc0[10], acc1[10];
#pragma unroll
        for (int p = 0; p < 10; p++) { acc0[p] = sBp[p]; acc1[p] = sBp[p]; }

#pragma unroll 4
        for (int i = 0; i < GL_; i++) {
            float2 xv = *(const float2*)&sX[i * PX_ + bl];   // conflict-free
            const ull xa = dup2(xv.x);
            const ull xb = dup2(xv.y);
            const ulonglong2* wq = (const ulonglong2*)&sW[i * OL_];
#pragma unroll
            for (int q = 0; q < 5; q++) {
                ulonglong2 w2 = wq[q];
                fma2(acc0[2*q+0], xa, w2.x); fma2(acc0[2*q+1], xa, w2.y);
                fma2(acc1[2*q+0], xb, w2.x); fma2(acc1[2*q+1], xb, w2.y);
            }
        }
        // tanh -> fp16 round -> stats (from rounded) + transposed store
        const long bg = (long)R + bl;               // global batch index
#pragma unroll
        for (int p = 0; p < 10; p++) {
            ull h0 = ftanh2(acc0[p]);               // row bl, features 2p,2p+1
            ull h1 = ftanh2(acc1[p]);               // row bl+1
            float a0, a1, b0, b1;
            unpack2(h0, a0, a1); unpack2(h1, b0, b1);
            __half2 ha = __floats2half2_rn(a0, b0); // feature 2p,   rows bl,bl+1
            __half2 hb = __floats2half2_rn(a1, b1); // feature 2p+1, rows bl,bl+1
            *(__half2*)&g_leaf_h[((long)s * OL_ + 2*p+0) * B_ + bg] = ha;
            *(__half2*)&g_leaf_h[((long)s * OL_ + 2*p+1) * B_ + bg] = hb;
            float2 fa = __half22float2(ha);
            float2 fb = __half22float2(hb);
            sum[p] = add2(sum[p], pack2(fa.x + fa.y, fb.x + fb.y));
            sq[p]  = add2(sq[p],  pack2(fmaf(fa.x, fa.x, fa.y * fa.y),
                                        fmaf(fb.x, fb.x, fb.y * fb.y)));
        }
    }

    float s20[OL_], q20[OL_];
#pragma unroll
    for (int p = 0; p < 10; p++) {
        unpack2(sum[p], s20[2*p], s20[2*p+1]);
        unpack2(sq[p],  q20[2*p], q20[2*p+1]);
    }
#pragma unroll
    for (int o = 0; o < OL_; o++) {
        for (int off = 16; off > 0; off >>= 1) {
            s20[o] += __shfl_down_sync(0xffffffffu, s20[o], off);
            q20[o] += __shfl_down_sync(0xffffffffu, q20[o], off);
        }
    }
    const int warp = tid >> 5, lane = tid & 31;
    if (lane == 0) {
#pragma unroll
        for (int o = 0; o < OL_; o++) { sRed[warp*40+o] = s20[o]; sRed[warp*40+20+o] = q20[o]; }
    }
    __syncthreads();
    if (tid < OL_) {
        float s1 = 0.f, s2 = 0.f;
        for (int w = 0; w < 4; w++) { s1 += sRed[w*40+tid]; s2 += sRed[w*40+20+tid]; }
        g_leaf_part[(s * 2 + c) * 40 + tid]      = s1;
        g_leaf_part[(s * 2 + c) * 40 + 20 + tid] = s2;
    }
}

// ============================================================================
// Kernel 2: finalize leaf BN + fold into mid weights/bias. grid=32 (per m).
// ============================================================================
__global__ __launch_bounds__(256) void k_prep_mid(
    const float* __restrict__ W_mid, const float* __restrict__ b_mid,
    const float* __restrict__ gam, const float* __restrict__ bet)
{
    const int m = blockIdx.x;
    const int tid = threadIdx.x;
    __shared__ float sA[C_ * OL_], sC[C_ * OL_];

    for (int idx = tid; idx < C_ * OL_; idx += 256) {   // grid-stride (320 > 256)
        const int s = m * C_ + idx / OL_;
        const int o = idx % OL_;
        const int base = (s * 2) * 40 + o;
        const float s1 = g_leaf_part[base] + g_leaf_part[base + 40];
        const float s2 = g_leaf_part[base + 20] + g_leaf_part[base + 60];
        const float mean = s1 * (1.f / B_);
        const float var  = s2 * (1.f / B_) - mean * mean;
        const float a = gam[s * OL_ + o] * rsqrtf(var + EPSF);
        sA[idx] = a;
        sC[idx] = bet[s * OL_ + o] - mean * a;
    }
    __syncthreads();

    for (int idx = tid; idx < IM_ * OM_; idx += 256) {
        const int i = idx / OM_;
        float a = (i < GM_) ? 1.f : sA[i - GM_];
        g_Wmid[m * IM_ * OM_ + idx] = a * W_mid[m * IM_ * OM_ + idx];
    }
    const int warp = tid >> 5, lane = tid & 31;
    for (int o = warp; o < OM_; o += 8) {
        float p = 0.f;
        for (int i = GM_ + lane; i < IM_; i += 32)
            p = fmaf(sC[i - GM_], W_mid[m * IM_ * OM_ + i * OM_ + o], p);
        for (int off = 16; off > 0; off >>= 1)
            p += __shfl_down_sync(0xffffffffu, p, off);
        if (lane == 0) g_bmid[m * OM_ + o] = b_mid[m * OM_ + o] + p;
    }
}

// ============================================================================
// Kernel 3: mid. grid(MC_=8, 32), 128 thr, 2 ADJACENT rows/thread (b=2t).
// Children read half2 (L2-resident) from transposed g_leaf_h.
// Writes g_mid_h TRANSPOSED fp16 + partial stats (from rounded).
// ============================================================================
__global__ __launch_bounds__(128) void k_mid(const float* __restrict__ x_mid)
{
    const int chunk = blockIdx.x;
    const int m = blockIdx.y;
    const int tid = threadIdx.x;
    const int b0 = chunk * 256 + 2 * tid;           // rows b0, b0+1

    __shared__ __align__(16) float sW[IM_ * OM_];
    __shared__ __align__(16) ull sBp[10];
    __shared__ float sRed[4 * 40];

    for (int i = tid; i < IM_ * OM_; i += 128) sW[i] = g_Wmid[m * IM_ * OM_ + i];
    if (tid < 10)
        sBp[tid] = pack2(g_bmid[m * OM_ + tid * 2], g_bmid[m * OM_ + tid * 2 + 1]);
    __syncthreads();

    ull acc0[10], acc1[10];
#pragma unroll
    for (int p = 0; p < 10; p++) { acc0[p] = sBp[p]; acc1[p] = sBp[p]; }

    // genes (rows 0..63): direct loads (2 adjacent rows)
    {
        const float4* xm0 = (const float4*)(x_mid + ((long)m * B_ + b0) * GM_);
        const float4* xm1 = (const float4*)(x_mid + ((long)m * B_ + b0 + 1) * GM_);
#pragma unroll 2
        for (int i4 = 0; i4 < GM_ / 4; i4++) {
            float4 v0 = xm0[i4], v1 = xm1[i4];
            float xs0[4] = { v0.x, v0.y, v0.z, v0.w };
            float xs1[4] = { v1.x, v1.y, v1.z, v1.w };
#pragma unroll
            for (int cc = 0; cc < 4; cc++) {
                const int i = i4 * 4 + cc;
                const ull xa = dup2(xs0[cc]);
                const ull xb = dup2(xs1[cc]);
                const ulonglong2* wq = (const ulonglong2*)&sW[i * OM_];
#pragma unroll
                for (int q = 0; q < 5; q++) {
                    ulonglong2 w2 = wq[q];
                    fma2(acc0[2*q+0], xa, w2.x); fma2(acc0[2*q+1], xa, w2.y);
                    fma2(acc1[2*q+0], xb, w2.x); fma2(acc1[2*q+1], xb, w2.y);
                }
            }
        }
    }
    // children (rows 64..383): half2 loads (2 rows per LDG.32, L2-resident)
#pragma unroll 1
    for (int j = 0; j < C_; j++) {
        const long fbase = ((long)(m * C_ + j)) * OL_;   // feature row base
        float2 xp[OL_];
#pragma unroll
        for (int e = 0; e < OL_; e++)
            xp[e] = __half22float2(*(const __half2*)&g_leaf_h[(fbase + e) * B_ + b0]);
        const int rbase = GM_ + j * OL_;
#pragma unroll
        for (int e = 0; e < OL_; e++) {
            const ull xa = dup2(xp[e].x);
            const ull xb = dup2(xp[e].y);
            const ulonglong2* wq = (const ulonglong2*)&sW[(rbase + e) * OM_];
#pragma unroll
            for (int q = 0; q < 5; q++) {
                ulonglong2 w2 = wq[q];
                fma2(acc0[2*q+0], xa, w2.x); fma2(acc0[2*q+1], xa, w2.y);
                fma2(acc1[2*q+0], xb, w2.x); fma2(acc1[2*q+1], xb, w2.y);
            }
        }
    }

    ull sum[10], sq[10];
#pragma unroll
    for (int p = 0; p < 10; p++) {
        ull h0 = ftanh2(acc0[p]);                   // row b0, features 2p,2p+1
        ull h1 = ftanh2(acc1[p]);                   // row b0+1
        float a0, a1, c0, c1;
        unpack2(h0, a0, a1); unpack2(h1, c0, c1);
        __half2 ha = __floats2half2_rn(a0, c0);     // feature 2p,   rows b0,b0+1
        __half2 hb = __floats2half2_rn(a1, c1);     // feature 2p+1
        *(__half2*)&g_mid_h[((long)m * OM_ + 2*p+0) * B_ + b0] = ha;
        *(__half2*)&g_mid_h[((long)m * OM_ + 2*p+1) * B_ + b0] = hb;
        float2 fa = __half22float2(ha);
        float2 fb = __half22float2(hb);
        sum[p] = pack2(fa.x + fa.y, fb.x + fb.y);
        sq[p]  = pack2(fmaf(fa.x, fa.x, fa.y * fa.y),
                       fmaf(fb.x, fb.x, fb.y * fb.y));
    }

    float s20[OM_], q20[OM_];
#pragma unroll
    for (int p = 0; p < 10; p++) {
        unpack2(sum[p], s20[2*p], s20[2*p+1]);
        unpack2(sq[p],  q20[2*p], q20[2*p+1]);
    }
#pragma unroll
    for (int o = 0; o < OM_; o++) {
        for (int off = 16; off > 0; off >>= 1) {
            s20[o] += __shfl_down_sync(0xffffffffu, s20[o], off);
            q20[o] += __shfl_down_sync(0xffffffffu, q20[o], off);
        }
    }
    const int warp = tid >> 5, lane = tid & 31;
    if (lane == 0) {
#pragma unroll
        for (int o = 0; o < OM_; o++) { sRed[warp*40+o] = s20[o]; sRed[warp*40+20+o] = q20[o]; }
    }
    __syncthreads();
    if (tid < OM_) {
        float s1 = 0.f, s2 = 0.f;
        for (int w = 0; w < 4; w++) { s1 += sRed[w*40+tid]; s2 += sRed[w*40+20+tid]; }
        g_mid_part[((m * MC_ + chunk) * OM_ + tid) * 2 + 0] = s1;
        g_mid_part[((m * MC_ + chunk) * OM_ + tid) * 2 + 1] = s2;
    }
}

// ============================================================================
// Kernel 4: root child partials. grid(16 kc, 16 bc), 128 thr, thread per b.
// Inline mid-BN finalize; interleaved load+normalize+FMA (no xn[] array).
// ============================================================================
__global__ __launch_bounds__(128) void k_rootp(
    const float* __restrict__ W_root,
    const float* __restrict__ gam, const float* __restrict__ bet)
{
    const int kc = blockIdx.x;
    const int bc = blockIdx.y;
    const int tid = threadIdx.x;
    const int b = bc * 128 + tid;

    __shared__ __align__(16) float sW[40 * 40];
    __shared__ float sA[40], sC[40];

    if (tid < 40) {                                   // inline BN finalize
        const int g = kc * 40 + tid;                  // child idx 0..639
        const int mm = g / OM_, o = g % OM_;
        float s1 = 0.f, s2 = 0.f;
#pragma unroll
        for (int ch = 0; ch < MC_; ch++) {
            s1 += g_mid_part[((mm * MC_ + ch) * OM_ + o) * 2 + 0];
            s2 += g_mid_part[((mm * MC_ + ch) * OM_ + o) * 2 + 1];
        }
        const float mean = s1 * (1.f / B_);
        const float var  = s2 * (1.f / B_) - mean * mean;
        const float a = gam[g] * rsqrtf(var + EPSF);
        sA[tid] = a;
        sC[tid] = bet[g] - mean * a;
    }
    for (int idx = tid; idx < 40 * 40; idx += 128) {
        const int kk = idx / 40, oo = idx % 40;
        sW[idx] = (oo < OR_) ? W_root[(GR_ + kc * 40 + kk) * OR_ + oo] : 0.f;
    }
    __syncthreads();

    ull acc[20];
#pragma unroll
    for (int p = 0; p < 20; p++) acc[p] = 0ull;
#pragma unroll 4
    for (int kk = 0; kk < 40; kk++) {
        const float x = __half2float(g_mid_h[((long)(kc * 40 + kk)) * B_ + b]);
        const ull xd = dup2(fmaf(x, sA[kk], sC[kk]));
        const ulonglong2* wq = (const ulonglong2*)&sW[kk * 40];
#pragma unroll
        for (int q = 0; q < 10; q++) {
            ulonglong2 w2 = wq[q];
            fma2(acc[2*q+0], xd, w2.x);
            fma2(acc[2*q+1], xd, w2.y);
        }
    }
#pragma unroll
    for (int p = 0; p < 20; p++) {
        float lo, hi; unpack2(acc[p], lo, hi);
        g_root_part[((long)(kc * 40 + 2*p+0)) * B_ + b] = lo;       // coalesced
        g_root_part[((long)(kc * 40 + 2*p+1)) * B_ + b] = hi;
    }
}

// ============================================================================
// Kernel 5: root gene partials (k=0..127). grid 16, 128 thr, thread per b.
// ============================================================================
__global__ __launch_bounds__(128) void k_rootgene(
    const float* __restrict__ x_root, const float* __restrict__ W_root)
{
    const int tid = threadIdx.x;
    const int b = blockIdx.x * 128 + tid;

    __shared__ __align__(16) float sW[GR_ * 40];
    for (int idx = tid; idx < GR_ * 40; idx += 128) {
        const int kk = idx / 40, oo = idx % 40;
        sW[idx] = (oo < OR_) ? W_root[kk * OR_ + oo] : 0.f;
    }
    __syncthreads();

    ull acc[20];
#pragma unroll
    for (int p = 0; p < 20; p++) acc[p] = 0ull;

    const float4* px = (const float4*)(x_root + (long)b * GR_);
#pragma unroll 1
    for (int k4 = 0; k4 < GR_ / 4; k4++) {
        float4 v = px[k4];
        float xs[4] = { v.x, v.y, v.z, v.w };
#pragma unroll
        for (int cc = 0; cc < 4; cc++) {
            const ull xd = dup2(xs[cc]);
            const ulonglong2* wq = (const ulonglong2*)&sW[(k4 * 4 + cc) * 40];
#pragma unroll
            for (int q = 0; q < 10; q++) {
                ulonglong2 w2 = wq[q];
                fma2(acc[2*q+0], xd, w2.x);
                fma2(acc[2*q+1], xd, w2.y);
            }
        }
    }
#pragma unroll
    for (int p = 0; p < 20; p++) {
        float lo, hi; unpack2(acc[p], lo, hi);
        g_root_part[((long)(16 * 40 + 2*p+0)) * B_ + b] = lo;
        g_root_part[((long)(16 * 40 + 2*p+1)) * B_ + b] = hi;
    }
}

// ============================================================================
// Kernel 6: root finalize: combine 17 partials + bias + tanh + BN stats +
// normalize + write out. grid(38) — one block per output column.
// ============================================================================
__global__ __launch_bounds__(256) void k_rootfin(
    const float* __restrict__ b_root, const float* __restrict__ gam,
    const float* __restrict__ bet, float* __restrict__ out)
{
    const int o = blockIdx.x;
    const int tid = threadIdx.x;
    const float bias = b_root[o];

    float h[8];
    float s1 = 0.f, s2 = 0.f;
#pragma unroll
    for (int w = 0; w < 8; w++) {
        const int b = w * 256 + tid;
        float v = bias;
#pragma unroll
        for (int kc = 0; kc < 17; kc++)
            v += g_root_part[((long)(kc * 40 + o)) * B_ + b];       // coalesced
        const float t = ftanh(v);
        h[w] = t;
        s1 += t; s2 = fmaf(t, t, s2);
    }
    for (int off = 16; off > 0; off >>= 1) {
        s1 += __shfl_down_sync(0xffffffffu, s1, off);
        s2 += __shfl_down_sync(0xffffffffu, s2, off);
    }
    __shared__ float r1[8], r2[8];
    __shared__ float sAC[2];
    if ((tid & 31) == 0) { r1[tid >> 5] = s1; r2[tid >> 5] = s2; }
    __syncthreads();
    if (tid == 0) {
        float t1 = 0.f, t2 = 0.f;
        for (int w = 0; w < 8; w++) { t1 += r1[w]; t2 += r2[w]; }
        const float mean = t1 * (1.f / B_);
        const float var  = t2 * (1.f / B_) - mean * mean;
        const float a = gam[o] * rsqrtf(var + EPSF);
        sAC[0] = a;
        sAC[1] = bet[o] - mean * a;
    }
    __syncthreads();
    const float a = sAC[0], c = sAC[1];
#pragma unroll
    for (int w = 0; w < 8; w++) {
        const int b = w * 256 + tid;
        out[(long)b * OR_ + o] = fmaf(h[w], a, c);
    }
}

// ============================================================================
extern "C" void kernel_launch(void* const* d_in, const int* in_sizes, int n_in,
                              void* d_out, int out_size)
{
    const float* x_leaf = (const float*)d_in[0];
    const float* x_mid  = (const float*)d_in[1];
    const float* x_root = (const float*)d_in[2];
    const float* W_leaf = (const float*)d_in[3];
    const float* b_leaf = (const float*)d_in[4];
    const float* gleaf  = (const float*)d_in[5];
    const float* beleaf = (const float*)d_in[6];
    const float* W_mid  = (const float*)d_in[7];
    const float* b_mid  = (const float*)d_in[8];
    const float* gmid   = (const float*)d_in[9];
    const float* bemid  = (const float*)d_in[10];
    const float* W_root = (const float*)d_in[11];
    const float* b_root = (const float*)d_in[12];
    const float* groot  = (const float*)d_in[13];
    const float* beroot = (const float*)d_in[14];
    float* out = (float*)d_out;

    k_leaf<<<dim3(2, S_), 128>>>(x_leaf, W_leaf, b_leaf);
    k_prep_mid<<<M_, 256>>>(W_mid, b_mid, gleaf, beleaf);
    k_mid<<<dim3(MC_, M_), 128>>>(x_mid);
    k_rootp<<<dim3(16, 16), 128>>>(W_root, gmid, bemid);
    k_rootgene<<<16, 128>>>(x_root, W_root);
    k_rootfin<<<OR_, 256>>>(b_root, groot, beroot, out);
}